// round 1
// baseline (speedup 1.0000x reference)
#include <cuda_runtime.h>
#include <math.h>

#define LL 512
#define CC 128
#define NROWS (LL*LL)   // 262144

// ---- scratch (device globals; no allocation allowed) ----
__device__ float g_X[NROWS*CC];     // normalized input x (reused for normalized einsum out)
__device__ float g_P[NROWS*5*CC];   // 5 raw projections
__device__ float g_Lb[NROWS*CC];    // gated+masked left
__device__ float g_Rb[NROWS*CC];    // gated+masked right
__device__ float g_Fg[NROWS*CC];    // sigmoid(final gate)
__device__ float g_O[NROWS*CC];     // einsum output (pre-norm)

__device__ __forceinline__ float sigf(float x) {
    return 1.0f / (1.0f + __expf(-x));
}

// ---------------- LayerNorm: one warp per row of 128 ----------------
__global__ void ln_kernel(const float* __restrict__ in,
                          const float* __restrict__ scale,
                          const float* __restrict__ bias,
                          float* __restrict__ out)
{
    int warp = (blockIdx.x * blockDim.x + threadIdx.x) >> 5;
    int lane = threadIdx.x & 31;
    if (warp >= NROWS) return;
    const float4 v = *(const float4*)(in + (size_t)warp * CC + lane * 4);
    float s  = v.x + v.y + v.z + v.w;
    float sq = v.x*v.x + v.y*v.y + v.z*v.z + v.w*v.w;
    #pragma unroll
    for (int o = 16; o > 0; o >>= 1) {
        s  += __shfl_xor_sync(0xffffffffu, s,  o);
        sq += __shfl_xor_sync(0xffffffffu, sq, o);
    }
    float mean = s * (1.0f / CC);
    float var  = sq * (1.0f / CC) - mean * mean;
    float rstd = rsqrtf(var + 1e-5f);
    float4 sc = *(const float4*)(scale + lane * 4);
    float4 bi = *(const float4*)(bias  + lane * 4);
    float4 r;
    r.x = (v.x - mean) * rstd * sc.x + bi.x;
    r.y = (v.y - mean) * rstd * sc.y + bi.y;
    r.z = (v.z - mean) * rstd * sc.z + bi.z;
    r.w = (v.w - mean) * rstd * sc.w + bi.w;
    *(float4*)(out + (size_t)warp * CC + lane * 4) = r;
}

// ---------------- SGEMM: (N x 128) @ (128 x 128) per blockIdx.y matrix ----------------
// Block tile 128x128, k-chunk 8, 256 threads, per-thread 8x8.
// Writes out[row*ldo + m*128 + c] = acc + bias[c], optionally * gate[row*128+c].
__global__ void __launch_bounds__(256) gemm_fused(
    const float* __restrict__ X,
    const float* __restrict__ w0, const float* __restrict__ w1,
    const float* __restrict__ w2, const float* __restrict__ w3,
    const float* __restrict__ w4,
    const float* __restrict__ b0, const float* __restrict__ b1,
    const float* __restrict__ b2, const float* __restrict__ b3,
    const float* __restrict__ b4,
    float* __restrict__ out, int ldo,
    const float* __restrict__ gate)
{
    __shared__ float As[8][128];
    __shared__ float Bs[8][128];
    const int m = blockIdx.y;
    const float* W = (m == 0) ? w0 : (m == 1) ? w1 : (m == 2) ? w2 : (m == 3) ? w3 : w4;
    const float* B = (m == 0) ? b0 : (m == 1) ? b1 : (m == 2) ? b2 : (m == 3) ? b3 : b4;
    const int r0  = blockIdx.x * 128;
    const int tid = threadIdx.x;
    const int tx  = tid & 15;       // column group (8 cols)
    const int ty  = tid >> 4;       // row group (8 rows)
    const int lr  = tid >> 1;       // A-load row (0..127)
    const int lk  = (tid & 1) * 4;  // A-load k offset
    const int bk  = tid >> 5;       // B-load k (0..7)
    const int bc  = (tid & 31) * 4; // B-load col

    float acc[8][8];
    #pragma unroll
    for (int i = 0; i < 8; i++)
        #pragma unroll
        for (int j = 0; j < 8; j++) acc[i][j] = 0.0f;

    for (int k0 = 0; k0 < CC; k0 += 8) {
        float4 a4 = *(const float4*)(X + (size_t)(r0 + lr) * CC + k0 + lk);
        As[lk + 0][lr] = a4.x;
        As[lk + 1][lr] = a4.y;
        As[lk + 2][lr] = a4.z;
        As[lk + 3][lr] = a4.w;
        *(float4*)(&Bs[bk][bc]) = *(const float4*)(W + (size_t)(k0 + bk) * CC + bc);
        __syncthreads();
        #pragma unroll
        for (int kk = 0; kk < 8; kk++) {
            float a[8], b[8];
            #pragma unroll
            for (int i = 0; i < 8; i++) a[i] = As[kk][ty * 8 + i];
            #pragma unroll
            for (int j = 0; j < 8; j++) b[j] = Bs[kk][tx * 8 + j];
            #pragma unroll
            for (int i = 0; i < 8; i++)
                #pragma unroll
                for (int j = 0; j < 8; j++)
                    acc[i][j] = fmaf(a[i], b[j], acc[i][j]);
        }
        __syncthreads();
    }

    float4 bl = *(const float4*)(B + tx * 8);
    float4 bh = *(const float4*)(B + tx * 8 + 4);
    #pragma unroll
    for (int i = 0; i < 8; i++) {
        int row = r0 + ty * 8 + i;
        float4 lo, hi;
        lo.x = acc[i][0] + bl.x; lo.y = acc[i][1] + bl.y;
        lo.z = acc[i][2] + bl.z; lo.w = acc[i][3] + bl.w;
        hi.x = acc[i][4] + bh.x; hi.y = acc[i][5] + bh.y;
        hi.z = acc[i][6] + bh.z; hi.w = acc[i][7] + bh.w;
        if (gate) {
            float4 gl = *(const float4*)(gate + (size_t)row * CC + tx * 8);
            float4 gh = *(const float4*)(gate + (size_t)row * CC + tx * 8 + 4);
            lo.x *= gl.x; lo.y *= gl.y; lo.z *= gl.z; lo.w *= gl.w;
            hi.x *= gh.x; hi.y *= gh.y; hi.z *= gh.z; hi.w *= gh.w;
        }
        float* op = out + (size_t)row * ldo + m * 128 + tx * 8;
        *(float4*)(op)     = lo;
        *(float4*)(op + 4) = hi;
    }
}

// ---------------- elementwise combine: gates + pair mask ----------------
__global__ void combine_kernel(const float* __restrict__ mask)
{
    int idx = blockIdx.x * blockDim.x + threadIdx.x;
    if (idx >= NROWS * 32) return;
    int n  = idx >> 5;
    int c4 = (idx & 31) << 2;
    const float* p = g_P + (size_t)n * 640;
    float4 pl  = *(const float4*)(p + c4);
    float4 pr  = *(const float4*)(p + 128 + c4);
    float4 plg = *(const float4*)(p + 256 + c4);
    float4 prg = *(const float4*)(p + 384 + c4);
    float4 pf  = *(const float4*)(p + 512 + c4);
    float pm = mask[n >> 9] * mask[n & 511];

    float4 lo, ro, fo;
    lo.x = pl.x * sigf(plg.x) * pm;  lo.y = pl.y * sigf(plg.y) * pm;
    lo.z = pl.z * sigf(plg.z) * pm;  lo.w = pl.w * sigf(plg.w) * pm;
    ro.x = pr.x * sigf(prg.x) * pm;  ro.y = pr.y * sigf(prg.y) * pm;
    ro.z = pr.z * sigf(prg.z) * pm;  ro.w = pr.w * sigf(prg.w) * pm;
    fo.x = sigf(pf.x); fo.y = sigf(pf.y); fo.z = sigf(pf.z); fo.w = sigf(pf.w);

    *(float4*)(g_Lb + (size_t)n * CC + c4) = lo;
    *(float4*)(g_Rb + (size_t)n * CC + c4) = ro;
    *(float4*)(g_Fg + (size_t)n * CC + c4) = fo;
}

// ---------------- einsum: out[i,j,c] = sum_k L[i,k,c] * R[j,k,c] ----------------
// Block tile: 32 i x 32 j x 32 c, k-chunk 4. 256 threads as (ti=4, tj=4, tc=16).
// Per-thread register tile: 8 i x 8 j x 2 c (float2 acc).
#define EKB 4
#define CPAD 36
__global__ void __launch_bounds__(256, 1) einsum_kernel()
{
    __shared__ float Ls[EKB][32][CPAD];
    __shared__ float Rs[EKB][32][CPAD];
    const int i0 = blockIdx.x * 32;
    const int j0 = blockIdx.y * 32;
    const int c0 = blockIdx.z * 32;
    const int tid = threadIdx.x;
    const int tc = tid >> 4;          // 0..15
    const int tj = (tid >> 2) & 3;    // 0..3
    const int ti = tid & 3;           // 0..3
    const int li = (tid >> 3) & 31;   // load row
    const int cq = tid & 7;           // load float4-in-row

    float2 acc[8][8];
    #pragma unroll
    for (int a = 0; a < 8; a++)
        #pragma unroll
        for (int b = 0; b < 8; b++) { acc[a][b].x = 0.0f; acc[a][b].y = 0.0f; }

    for (int k0 = 0; k0 < LL; k0 += EKB) {
        #pragma unroll
        for (int q = 0; q < EKB; q++) {
            const int kk = q;
            float4 lv = *(const float4*)(g_Lb + ((size_t)(i0 + li) * LL + k0 + kk) * CC + c0 + cq * 4);
            *(float4*)(&Ls[kk][li][cq * 4]) = lv;
            float4 rv = *(const float4*)(g_Rb + ((size_t)(j0 + li) * LL + k0 + kk) * CC + c0 + cq * 4);
            *(float4*)(&Rs[kk][li][cq * 4]) = rv;
        }
        __syncthreads();
        #pragma unroll
        for (int kk = 0; kk < EKB; kk++) {
            float2 lL[8], rR[8];
            #pragma unroll
            for (int ii = 0; ii < 8; ii++)
                lL[ii] = *(const float2*)(&Ls[kk][ti + 4 * ii][tc * 2]);
            #pragma unroll
            for (int jj = 0; jj < 8; jj++)
                rR[jj] = *(const float2*)(&Rs[kk][tj + 4 * jj][tc * 2]);
            #pragma unroll
            for (int ii = 0; ii < 8; ii++)
                #pragma unroll
                for (int jj = 0; jj < 8; jj++) {
                    acc[ii][jj].x = fmaf(lL[ii].x, rR[jj].x, acc[ii][jj].x);
                    acc[ii][jj].y = fmaf(lL[ii].y, rR[jj].y, acc[ii][jj].y);
                }
        }
        __syncthreads();
    }

    #pragma unroll
    for (int ii = 0; ii < 8; ii++) {
        int i = i0 + ti + 4 * ii;
        #pragma unroll
        for (int jj = 0; jj < 8; jj++) {
            int j = j0 + tj + 4 * jj;
            *(float2*)(g_O + ((size_t)i * LL + j) * CC + c0 + tc * 2) = acc[ii][jj];
        }
    }
}

// ---------------- host launch ----------------
extern "C" void kernel_launch(void* const* d_in, const int* in_sizes, int n_in,
                              void* d_out, int out_size)
{
    const float* act         = (const float*)d_in[0];
    const float* mask        = (const float*)d_in[1];
    const float* norm_scale  = (const float*)d_in[2];
    const float* norm_bias   = (const float*)d_in[3];
    const float* w_left      = (const float*)d_in[4];
    const float* b_left      = (const float*)d_in[5];
    const float* w_right     = (const float*)d_in[6];
    const float* b_right     = (const float*)d_in[7];
    const float* w_lgate     = (const float*)d_in[8];
    const float* b_lgate     = (const float*)d_in[9];
    const float* w_rgate     = (const float*)d_in[10];
    const float* b_rgate     = (const float*)d_in[11];
    const float* fnorm_scale = (const float*)d_in[12];
    const float* fnorm_bias  = (const float*)d_in[13];
    const float* w_out       = (const float*)d_in[14];
    const float* b_out       = (const float*)d_in[15];
    const float* w_fgate     = (const float*)d_in[16];
    const float* b_fgate     = (const float*)d_in[17];

    float *X, *P, *Fg, *O;
    cudaGetSymbolAddress((void**)&X,  g_X);
    cudaGetSymbolAddress((void**)&P,  g_P);
    cudaGetSymbolAddress((void**)&Fg, g_Fg);
    cudaGetSymbolAddress((void**)&O,  g_O);

    // 1) x = LN(act)
    ln_kernel<<<NROWS / 8, 256>>>(act, norm_scale, norm_bias, X);

    // 2) 5 projections: P[n, 0:640]
    gemm_fused<<<dim3(NROWS / 128, 5), 256>>>(
        X, w_left, w_right, w_lgate, w_rgate, w_fgate,
        b_left, b_right, b_lgate, b_rgate, b_fgate,
        P, 640, nullptr);

    // 3) gates + pair mask -> Lb, Rb, Fg
    combine_kernel<<<(NROWS * 32) / 256, 256>>>(mask);

    // 4) einsum bikc,bjkc->bijc
    einsum_kernel<<<dim3(LL / 32, LL / 32, CC / 32), 256>>>();

    // 5) LN(einsum out) -> reuse X
    ln_kernel<<<NROWS / 8, 256>>>(O, fnorm_scale, fnorm_bias, X);

    // 6) output projection + final gate
    gemm_fused<<<dim3(NROWS / 128, 1), 256>>>(
        X, w_out, w_out, w_out, w_out, w_out,
        b_out, b_out, b_out, b_out, b_out,
        (float*)d_out, 128, Fg);
}

// round 4
// speedup vs baseline: 3.0433x; 3.0433x over previous
#include <cuda_runtime.h>
#include <cstdint>
#include <math.h>

#define LL 512
#define CC 128
#define NROWS (LL*LL)   // 262144

// ---- scratch (device globals; no allocation allowed) ----
__device__ float g_X[NROWS*CC];     // normalized input (n-major); reused for normalized einsum out
__device__ float g_P[NROWS*5*CC];   // 5 raw projections (n-major, 640 per row)
__device__ float g_Lt[CC*NROWS];    // left  gated+masked, c-major planes [c][i*512+k], tf32-rounded
__device__ float g_Rt[CC*NROWS];    // right gated+masked, c-major planes [c][j*512+k], tf32-rounded
__device__ float g_Fg[NROWS*CC];    // sigmoid(final gate), n-major
__device__ float g_Ot[CC*NROWS];    // einsum output, c-major planes [c][i*512+j]

__device__ __forceinline__ float sigf(float x) {
    return 1.0f / (1.0f + __expf(-x));
}
__device__ __forceinline__ float tf32r(float x) {
    uint32_t y;
    asm("cvt.rna.tf32.f32 %0, %1;" : "=r"(y) : "f"(x));
    return __uint_as_float(y);
}
__device__ __forceinline__ void mma_tf32(float* c, const uint32_t* a, const uint32_t* b) {
    asm volatile(
        "mma.sync.aligned.m16n8k8.row.col.f32.tf32.tf32.f32 "
        "{%0,%1,%2,%3}, {%4,%5,%6,%7}, {%8,%9}, {%0,%1,%2,%3};"
        : "+f"(c[0]), "+f"(c[1]), "+f"(c[2]), "+f"(c[3])
        : "r"(a[0]), "r"(a[1]), "r"(a[2]), "r"(a[3]), "r"(b[0]), "r"(b[1]));
}

// ---------------- LayerNorm: one warp per row of 128 ----------------
__global__ void ln_kernel(const float* __restrict__ in,
                          const float* __restrict__ scale,
                          const float* __restrict__ bias,
                          float* __restrict__ out)
{
    int warp = (blockIdx.x * blockDim.x + threadIdx.x) >> 5;
    int lane = threadIdx.x & 31;
    if (warp >= NROWS) return;
    const float4 v = *(const float4*)(in + (size_t)warp * CC + lane * 4);
    float s  = v.x + v.y + v.z + v.w;
    float sq = v.x*v.x + v.y*v.y + v.z*v.z + v.w*v.w;
    #pragma unroll
    for (int o = 16; o > 0; o >>= 1) {
        s  += __shfl_xor_sync(0xffffffffu, s,  o);
        sq += __shfl_xor_sync(0xffffffffu, sq, o);
    }
    float mean = s * (1.0f / CC);
    float var  = sq * (1.0f / CC) - mean * mean;
    float rstd = rsqrtf(var + 1e-5f);
    float4 sc = *(const float4*)(scale + lane * 4);
    float4 bi = *(const float4*)(bias  + lane * 4);
    float4 r;
    r.x = (v.x - mean) * rstd * sc.x + bi.x;
    r.y = (v.y - mean) * rstd * sc.y + bi.y;
    r.z = (v.z - mean) * rstd * sc.z + bi.z;
    r.w = (v.w - mean) * rstd * sc.w + bi.w;
    *(float4*)(out + (size_t)warp * CC + lane * 4) = r;
}

// ---------------- tf32 mma GEMM: (N x 128) @ (128 x 128) per blockIdx.y weight ----------------
// Block: 128 rows x 128 cols, 256 threads = 8 warps (2 m x 4 n), warp tile 64x32.
// k-chunk 16. Xs stride 20, Ws[k][n] stride 136 (conflict-free fragment reads).
__global__ void __launch_bounds__(256) gemm_mma(
    const float* __restrict__ X,
    const float* __restrict__ w0, const float* __restrict__ w1,
    const float* __restrict__ w2, const float* __restrict__ w3,
    const float* __restrict__ w4,
    const float* __restrict__ b0, const float* __restrict__ b1,
    const float* __restrict__ b2, const float* __restrict__ b3,
    const float* __restrict__ b4,
    float* __restrict__ out, int ldo,
    const float* __restrict__ gate)
{
    __shared__ float Xs[128 * 20];
    __shared__ float Ws[16 * 136];
    const int m = blockIdx.y;
    const float* W = (m == 0) ? w0 : (m == 1) ? w1 : (m == 2) ? w2 : (m == 3) ? w3 : w4;
    const float* B = (m == 0) ? b0 : (m == 1) ? b1 : (m == 2) ? b2 : (m == 3) ? b3 : b4;
    const int r0   = blockIdx.x * 128;
    const int tid  = threadIdx.x;
    const int wid  = tid >> 5;
    const int lane = tid & 31;
    const int warp_m = wid >> 2;       // 0..1
    const int warp_n = wid & 3;        // 0..3
    const int lr = lane >> 2;          // 0..7
    const int lc = lane & 3;           // 0..3

    float acc[16][4];
    #pragma unroll
    for (int t = 0; t < 16; t++)
        #pragma unroll
        for (int q = 0; q < 4; q++) acc[t][q] = 0.0f;

    for (int k0 = 0; k0 < CC; k0 += 16) {
        // load X tile: 128 rows x 16 k, tf32-rounded
        #pragma unroll
        for (int u = 0; u < 2; u++) {
            int idx = tid + u * 256;       // 0..511
            int r = idx >> 2;
            int q = idx & 3;
            float4 v = *(const float4*)(X + (size_t)(r0 + r) * CC + k0 + q * 4);
            v.x = tf32r(v.x); v.y = tf32r(v.y); v.z = tf32r(v.z); v.w = tf32r(v.w);
            *(float4*)(&Xs[r * 20 + q * 4]) = v;
        }
        // load W chunk: 16 k x 128 n, tf32-rounded
        #pragma unroll
        for (int u = 0; u < 2; u++) {
            int idx = tid + u * 256;       // 0..511
            int k = idx >> 5;
            int q = idx & 31;
            float4 v = *(const float4*)(W + (size_t)(k0 + k) * CC + q * 4);
            v.x = tf32r(v.x); v.y = tf32r(v.y); v.z = tf32r(v.z); v.w = tf32r(v.w);
            *(float4*)(&Ws[k * 136 + q * 4]) = v;
        }
        __syncthreads();
        #pragma unroll
        for (int ks = 0; ks < 16; ks += 8) {
            uint32_t a[4][4], b[4][2];
            #pragma unroll
            for (int mt = 0; mt < 4; mt++) {
                int rb = (warp_m * 64 + mt * 16 + lr) * 20 + ks + lc;
                a[mt][0] = __float_as_uint(Xs[rb]);
                a[mt][1] = __float_as_uint(Xs[rb + 8 * 20]);
                a[mt][2] = __float_as_uint(Xs[rb + 4]);
                a[mt][3] = __float_as_uint(Xs[rb + 8 * 20 + 4]);
            }
            #pragma unroll
            for (int nt = 0; nt < 4; nt++) {
                int nb = warp_n * 32 + nt * 8 + lr;
                b[nt][0] = __float_as_uint(Ws[(ks + lc) * 136 + nb]);
                b[nt][1] = __float_as_uint(Ws[(ks + 4 + lc) * 136 + nb]);
            }
            #pragma unroll
            for (int mt = 0; mt < 4; mt++)
                #pragma unroll
                for (int nt = 0; nt < 4; nt++)
                    mma_tf32(acc[mt * 4 + nt], a[mt], b[nt]);
        }
        __syncthreads();
    }

    // epilogue: bias (+ optional gate), write float2 pairs
    #pragma unroll
    for (int mt = 0; mt < 4; mt++) {
        #pragma unroll
        for (int nt = 0; nt < 4; nt++) {
            int col = warp_n * 32 + nt * 8 + lc * 2;
            float2 bb = *(const float2*)(B + col);
            #pragma unroll
            for (int h = 0; h < 2; h++) {
                int row = r0 + warp_m * 64 + mt * 16 + lr + h * 8;
                float2 v;
                v.x = acc[mt * 4 + nt][h * 2 + 0] + bb.x;
                v.y = acc[mt * 4 + nt][h * 2 + 1] + bb.y;
                if (gate) {
                    float2 gv = *(const float2*)(gate + (size_t)row * CC + col);
                    v.x *= gv.x; v.y *= gv.y;
                }
                *(float2*)(out + (size_t)row * ldo + m * 128 + col) = v;
            }
        }
    }
}

// ---------------- combine + transpose: P -> Lt, Rt (c-major, tf32-rounded) + Fg ----------------
__global__ void __launch_bounds__(256) combine_transpose(const float* __restrict__ mask)
{
    __shared__ float tile[64][132];
    const int n0 = blockIdx.x * 64;
    const int t  = threadIdx.x;

    // ---- Pass L ----
    #pragma unroll
    for (int p = 0; p < 8; p++) {
        int idx = t + p * 256;
        int nl  = idx >> 5;
        int c4  = (idx & 31) * 4;
        int n   = n0 + nl;
        const float* pr = g_P + (size_t)n * 640;
        float4 pl  = *(const float4*)(pr + c4);
        float4 plg = *(const float4*)(pr + 256 + c4);
        float4 pf  = *(const float4*)(pr + 512 + c4);
        float pm = mask[n >> 9] * mask[n & 511];
        tile[nl][c4 + 0] = tf32r(pl.x * sigf(plg.x) * pm);
        tile[nl][c4 + 1] = tf32r(pl.y * sigf(plg.y) * pm);
        tile[nl][c4 + 2] = tf32r(pl.z * sigf(plg.z) * pm);
        tile[nl][c4 + 3] = tf32r(pl.w * sigf(plg.w) * pm);
        float4 fo;
        fo.x = sigf(pf.x); fo.y = sigf(pf.y); fo.z = sigf(pf.z); fo.w = sigf(pf.w);
        *(float4*)(g_Fg + (size_t)n * CC + c4) = fo;
    }
    __syncthreads();
    {
        int c = t >> 1, h = t & 1;
        float* dst = g_Lt + (size_t)c * NROWS + n0 + h * 32;
        #pragma unroll
        for (int q = 0; q < 8; q++) {
            int nb = h * 32 + q * 4;
            float4 v;
            v.x = tile[nb + 0][c]; v.y = tile[nb + 1][c];
            v.z = tile[nb + 2][c]; v.w = tile[nb + 3][c];
            *(float4*)(dst + q * 4) = v;
        }
    }
    __syncthreads();

    // ---- Pass R ----
    #pragma unroll
    for (int p = 0; p < 8; p++) {
        int idx = t + p * 256;
        int nl  = idx >> 5;
        int c4  = (idx & 31) * 4;
        int n   = n0 + nl;
        const float* pr = g_P + (size_t)n * 640;
        float4 prv = *(const float4*)(pr + 128 + c4);
        float4 prg = *(const float4*)(pr + 384 + c4);
        float pm = mask[n >> 9] * mask[n & 511];
        tile[nl][c4 + 0] = tf32r(prv.x * sigf(prg.x) * pm);
        tile[nl][c4 + 1] = tf32r(prv.y * sigf(prg.y) * pm);
        tile[nl][c4 + 2] = tf32r(prv.z * sigf(prg.z) * pm);
        tile[nl][c4 + 3] = tf32r(prv.w * sigf(prg.w) * pm);
    }
    __syncthreads();
    {
        int c = t >> 1, h = t & 1;
        float* dst = g_Rt + (size_t)c * NROWS + n0 + h * 32;
        #pragma unroll
        for (int q = 0; q < 8; q++) {
            int nb = h * 32 + q * 4;
            float4 v;
            v.x = tile[nb + 0][c]; v.y = tile[nb + 1][c];
            v.z = tile[nb + 2][c]; v.w = tile[nb + 3][c];
            *(float4*)(dst + q * 4) = v;
        }
    }
}

// ---------------- einsum via mma.sync tf32: per c-plane, D = Lt_c @ Rt_c^T ----------------
// Block 128i x 128j, 256 threads = 8 warps (2x4), warp tile 64x32, k-chunk 16.
__global__ void __launch_bounds__(256) einsum_mma()
{
    __shared__ float As[128 * 20];
    __shared__ float Bs[128 * 20];
    const int c  = blockIdx.z;
    const int i0 = blockIdx.x * 128;
    const int j0 = blockIdx.y * 128;
    const int tid  = threadIdx.x;
    const int wid  = tid >> 5;
    const int lane = tid & 31;
    const int warp_m = wid >> 2;
    const int warp_n = wid & 3;
    const int lr = lane >> 2;
    const int lc = lane & 3;

    const float* Ap = g_Lt + (size_t)c * NROWS + (size_t)i0 * 512;
    const float* Bp = g_Rt + (size_t)c * NROWS + (size_t)j0 * 512;

    float acc[16][4];
    #pragma unroll
    for (int t = 0; t < 16; t++)
        #pragma unroll
        for (int q = 0; q < 4; q++) acc[t][q] = 0.0f;

    for (int k0 = 0; k0 < LL; k0 += 16) {
        #pragma unroll
        for (int u = 0; u < 2; u++) {
            int idx = tid + u * 256;       // 0..511
            int r = idx >> 2;
            int q = idx & 3;
            *(float4*)(&As[r * 20 + q * 4]) = *(const float4*)(Ap + (size_t)r * 512 + k0 + q * 4);
            *(float4*)(&Bs[r * 20 + q * 4]) = *(const float4*)(Bp + (size_t)r * 512 + k0 + q * 4);
        }
        __syncthreads();
        #pragma unroll
        for (int ks = 0; ks < 16; ks += 8) {
            uint32_t a[4][4], b[4][2];
            #pragma unroll
            for (int mt = 0; mt < 4; mt++) {
                int rb = (warp_m * 64 + mt * 16 + lr) * 20 + ks + lc;
                a[mt][0] = __float_as_uint(As[rb]);
                a[mt][1] = __float_as_uint(As[rb + 8 * 20]);
                a[mt][2] = __float_as_uint(As[rb + 4]);
                a[mt][3] = __float_as_uint(As[rb + 8 * 20 + 4]);
            }
            #pragma unroll
            for (int nt = 0; nt < 4; nt++) {
                int rb = (warp_n * 32 + nt * 8 + lr) * 20 + ks + lc;
                b[nt][0] = __float_as_uint(Bs[rb]);
                b[nt][1] = __float_as_uint(Bs[rb + 4]);
            }
            #pragma unroll
            for (int mt = 0; mt < 4; mt++)
                #pragma unroll
                for (int nt = 0; nt < 4; nt++)
                    mma_tf32(acc[mt * 4 + nt], a[mt], b[nt]);
        }
        __syncthreads();
    }

    float* Op = g_Ot + (size_t)c * NROWS;
    #pragma unroll
    for (int mt = 0; mt < 4; mt++) {
        #pragma unroll
        for (int nt = 0; nt < 4; nt++) {
            int col = j0 + warp_n * 32 + nt * 8 + lc * 2;
            #pragma unroll
            for (int h = 0; h < 2; h++) {
                int row = i0 + warp_m * 64 + mt * 16 + lr + h * 8;
                float2 v;
                v.x = acc[mt * 4 + nt][h * 2 + 0];
                v.y = acc[mt * 4 + nt][h * 2 + 1];
                *(float2*)(Op + (size_t)row * 512 + col) = v;
            }
        }
    }
}

// ---------------- transpose + LayerNorm: Ot (c-major) -> X (n-major, normalized) ----------------
__global__ void __launch_bounds__(256) trans_ln(const float* __restrict__ scale,
                                                const float* __restrict__ bias,
                                                float* __restrict__ outX)
{
    __shared__ float tile[128][68];
    const int n0 = blockIdx.x * 64;
    const int t  = threadIdx.x;
    const int w  = t >> 5;
    const int l  = t & 31;

    #pragma unroll
    for (int p = 0; p < 8; p++) {
        int idx = t + p * 256;          // 0..2047 = 128 c x 16 float4
        int cc = idx >> 4;
        int q  = idx & 15;
        float4 v = *(const float4*)(g_Ot + (size_t)cc * NROWS + n0 + q * 4);
        tile[cc][q * 4 + 0] = v.x;
        tile[cc][q * 4 + 1] = v.y;
        tile[cc][q * 4 + 2] = v.z;
        tile[cc][q * 4 + 3] = v.w;
    }
    __syncthreads();

    float4 sc = *(const float4*)(scale + l * 4);
    float4 bi = *(const float4*)(bias  + l * 4);
    #pragma unroll
    for (int rr = 0; rr < 8; rr++) {
        int nl = w * 8 + rr;
        float v0 = tile[l * 4 + 0][nl];
        float v1 = tile[l * 4 + 1][nl];
        float v2 = tile[l * 4 + 2][nl];
        float v3 = tile[l * 4 + 3][nl];
        float s  = v0 + v1 + v2 + v3;
        float sq = v0*v0 + v1*v1 + v2*v2 + v3*v3;
        #pragma unroll
        for (int o = 16; o > 0; o >>= 1) {
            s  += __shfl_xor_sync(0xffffffffu, s,  o);
            sq += __shfl_xor_sync(0xffffffffu, sq, o);
        }
        float mean = s * (1.0f / CC);
        float var  = sq * (1.0f / CC) - mean * mean;
        float rstd = rsqrtf(var + 1e-5f);
        float4 r;
        r.x = (v0 - mean) * rstd * sc.x + bi.x;
        r.y = (v1 - mean) * rstd * sc.y + bi.y;
        r.z = (v2 - mean) * rstd * sc.z + bi.z;
        r.w = (v3 - mean) * rstd * sc.w + bi.w;
        *(float4*)(outX + (size_t)(n0 + nl) * CC + l * 4) = r;
    }
}

// ---------------- host launch ----------------
extern "C" void kernel_launch(void* const* d_in, const int* in_sizes, int n_in,
                              void* d_out, int out_size)
{
    const float* act         = (const float*)d_in[0];
    const float* mask        = (const float*)d_in[1];
    const float* norm_scale  = (const float*)d_in[2];
    const float* norm_bias   = (const float*)d_in[3];
    const float* w_left      = (const float*)d_in[4];
    const float* b_left      = (const float*)d_in[5];
    const float* w_right     = (const float*)d_in[6];
    const float* b_right     = (const float*)d_in[7];
    const float* w_lgate     = (const float*)d_in[8];
    const float* b_lgate     = (const float*)d_in[9];
    const float* w_rgate     = (const float*)d_in[10];
    const float* b_rgate     = (const float*)d_in[11];
    const float* fnorm_scale = (const float*)d_in[12];
    const float* fnorm_bias  = (const float*)d_in[13];
    const float* w_out       = (const float*)d_in[14];
    const float* b_out       = (const float*)d_in[15];
    const float* w_fgate     = (const float*)d_in[16];
    const float* b_fgate     = (const float*)d_in[17];

    float *X, *P, *Fg;
    cudaGetSymbolAddress((void**)&X,  g_X);
    cudaGetSymbolAddress((void**)&P,  g_P);
    cudaGetSymbolAddress((void**)&Fg, g_Fg);

    // 1) x = LN(act)
    ln_kernel<<<NROWS / 8, 256>>>(act, norm_scale, norm_bias, X);

    // 2) 5 projections -> P (tf32 tensor cores)
    gemm_mma<<<dim3(NROWS / 128, 5), 256>>>(
        X, w_left, w_right, w_lgate, w_rgate, w_fgate,
        b_left, b_right, b_lgate, b_rgate, b_fgate,
        P, 640, nullptr);

    // 3) gates + mask + c-major transpose (tf32-rounded) -> Lt, Rt; also Fg
    combine_transpose<<<NROWS / 64, 256>>>(mask);

    // 4) einsum on tensor cores (tf32), per-channel 512x512x512 GEMMs -> Ot (c-major)
    einsum_mma<<<dim3(4, 4, CC), 256>>>();

    // 5) transpose back + LN -> X (n-major)
    trans_ln<<<NROWS / 64, 256>>>(fnorm_scale, fnorm_bias, X);

    // 6) output projection + final gate (tf32 tensor cores)
    gemm_mma<<<dim3(NROWS / 128, 1), 256>>>(
        X, w_out, w_out, w_out, w_out, w_out,
        b_out, b_out, b_out, b_out, b_out,
        (float*)d_out, 128, Fg);
}